// round 1
// baseline (speedup 1.0000x reference)
#include <cuda_runtime.h>

typedef unsigned long long ull;

#define HS 68            // smem row stride (floats) for activation buffers
#define TILE_M 64
#define NTHREADS 256

__device__ __forceinline__ ull fma2(ull a, ull b, ull c) {
    ull d;
    asm("fma.rn.f32x2 %0, %1, %2, %3;" : "=l"(d) : "l"(a), "l"(b), "l"(c));
    return d;
}
__device__ __forceinline__ ull dup2(float x) {
    ull d;
    asm("mov.b64 %0, {%1, %1};" : "=l"(d) : "f"(x));
    return d;
}
__device__ __forceinline__ float2 unpack2(ull v) {
    float2 f;
    asm("mov.b64 {%0, %1}, %2;" : "=f"(f.x), "=f"(f.y) : "l"(v));
    return f;
}

__device__ __forceinline__ void mat3mul(float* C, const float* A, const float* Bm) {
    #pragma unroll
    for (int i = 0; i < 3; i++) {
        #pragma unroll
        for (int j = 0; j < 3; j++) {
            C[i*3 + j] = A[i*3 + 0]*Bm[0*3 + j] + A[i*3 + 1]*Bm[1*3 + j] + A[i*3 + 2]*Bm[2*3 + j];
        }
    }
}

// Dense layer + ReLU: hout[o][r] = relu(b[o] + sum_k hin[k][r] * w[o*KD + k])
// Thread (rg, ug) computes rows 4*rg..4*rg+3, units 8*ug..8*ug+7.
// f32x2 packs adjacent rows (lo = even row, hi = odd row); weight is broadcast-duplicated.
template<int KD>
__device__ __forceinline__ void dense_relu_layer(
    const float* __restrict__ hin,   // [KD][HS] k-major
    const float* __restrict__ wsm,   // [128][KD] o-major (as in gmem)
    const float* __restrict__ bsm,   // [128]
    float* __restrict__ hout,        // [128][HS]
    int rg, int ug)
{
    ull acc[2][8];
    #pragma unroll
    for (int p = 0; p < 2; p++)
        #pragma unroll
        for (int u = 0; u < 8; u++) acc[p][u] = 0ull;

    const float* hbase = hin + 4*rg;
    const float* wbase = wsm + (8*ug)*KD;

    #pragma unroll 2
    for (int k = 0; k < KD; k += 4) {
        ulonglong2 hA = *(const ulonglong2*)(hbase + (k+0)*HS);
        ulonglong2 hB = *(const ulonglong2*)(hbase + (k+1)*HS);
        ulonglong2 hC = *(const ulonglong2*)(hbase + (k+2)*HS);
        ulonglong2 hD = *(const ulonglong2*)(hbase + (k+3)*HS);
        #pragma unroll
        for (int u = 0; u < 8; u++) {
            float4 wv = *(const float4*)(wbase + u*KD + k);
            ull w0 = dup2(wv.x), w1 = dup2(wv.y), w2 = dup2(wv.z), w3 = dup2(wv.w);
            acc[0][u] = fma2(hA.x, w0, acc[0][u]);
            acc[1][u] = fma2(hA.y, w0, acc[1][u]);
            acc[0][u] = fma2(hB.x, w1, acc[0][u]);
            acc[1][u] = fma2(hB.y, w1, acc[1][u]);
            acc[0][u] = fma2(hC.x, w2, acc[0][u]);
            acc[1][u] = fma2(hC.y, w2, acc[1][u]);
            acc[0][u] = fma2(hD.x, w3, acc[0][u]);
            acc[1][u] = fma2(hD.y, w3, acc[1][u]);
        }
    }
    #pragma unroll
    for (int u = 0; u < 8; u++) {
        int o = 8*ug + u;
        float b = bsm[o];
        float2 p0 = unpack2(acc[0][u]);
        float2 p1 = unpack2(acc[1][u]);
        float4 v;
        v.x = fmaxf(p0.x + b, 0.f);
        v.y = fmaxf(p0.y + b, 0.f);
        v.z = fmaxf(p1.x + b, 0.f);
        v.w = fmaxf(p1.y + b, 0.f);
        *(float4*)(hout + o*HS + 4*rg) = v;
    }
}

__global__ void __launch_bounds__(NTHREADS, 1)
l2t_kernel(const float* __restrict__ y,
           const float* __restrict__ ow0, const float* __restrict__ ob0,
           const float* __restrict__ ow1, const float* __restrict__ ob1,
           const float* __restrict__ ow2, const float* __restrict__ ob2,
           const float* __restrict__ tw0, const float* __restrict__ tb0,
           const float* __restrict__ tw1, const float* __restrict__ tb1,
           const float* __restrict__ tw2, const float* __restrict__ tb2,
           float* __restrict__ out)
{
    extern __shared__ float sm[];
    float* ws0 = sm;                    // 128*32
    float* ws1 = ws0 + 128*32;          // 128*128
    float* ws2 = ws1 + 128*128;         // 12*128 (<=9 used)
    float* bs0 = ws2 + 12*128;          // 128
    float* bs1 = bs0 + 128;             // 128
    float* bs2 = bs1 + 128;             // 16
    float* xs  = bs2 + 16;              // 32*HS
    float* hb0 = xs  + 32*HS;           // 128*HS
    float* hb1 = hb0 + 128*HS;          // 128*HS
    float* o2  = hb1 + 128*HS;          // 64*16

    const int tid = threadIdx.x;
    const int rg  = tid & 15;           // row group: rows 4*rg .. 4*rg+3
    const int ug  = tid >> 4;           // unit group: units 8*ug .. 8*ug+7
    const int row0 = blockIdx.x * TILE_M;

    #pragma unroll 1
    for (int ph = 0; ph < 2; ++ph) {
        const float* w0 = ph ? tw0 : ow0;  const float* b0 = ph ? tb0 : ob0;
        const float* w1 = ph ? tw1 : ow1;  const float* b1 = ph ? tb1 : ob1;
        const float* w2 = ph ? tw2 : ow2;  const float* b2 = ph ? tb2 : ob2;
        const int nout = ph ? 3 : 9;

        __syncthreads();   // previous phase fully consumed smem
        // Stage weights (coalesced gmem reads, coalesced smem stores)
        for (int i = tid; i < 128*32;  i += NTHREADS) ws0[i] = w0[i];
        for (int i = tid; i < 128*128; i += NTHREADS) ws1[i] = w1[i];
        for (int i = tid; i < nout*128; i += NTHREADS) ws2[i] = w2[i];
        if (tid < 128) { bs0[tid] = b0[tid]; bs1[tid] = b1[tid]; }
        if (tid < 16)  bs2[tid] = (tid < nout) ? b2[tid] : 0.f;
        // Stage x tile transposed to k-major: xs[k][r]
        for (int i = tid; i < TILE_M*32; i += NTHREADS) {
            int r = i >> 5, k = i & 31;
            xs[k*HS + r] = y[(size_t)(row0 + r)*64 + ph*32 + k];
        }
        __syncthreads();

        dense_relu_layer<32>(xs, ws0, bs0, hb0, rg, ug);
        __syncthreads();
        dense_relu_layer<128>(hb0, ws1, bs1, hb1, rg, ug);
        __syncthreads();

        // Layer 2 (no relu): one output unit per thread (ug < nout), 4 rows
        if (ug < nout) {
            ull a0 = 0ull, a1 = 0ull;
            const float* hbase = hb1 + 4*rg;
            const float* wbase = ws2 + ug*128;
            #pragma unroll
            for (int k = 0; k < 128; k += 4) {
                ulonglong2 hA = *(const ulonglong2*)(hbase + (k+0)*HS);
                ulonglong2 hB = *(const ulonglong2*)(hbase + (k+1)*HS);
                ulonglong2 hC = *(const ulonglong2*)(hbase + (k+2)*HS);
                ulonglong2 hD = *(const ulonglong2*)(hbase + (k+3)*HS);
                float4 wv = *(const float4*)(wbase + k);
                ull w0d = dup2(wv.x), w1d = dup2(wv.y), w2d = dup2(wv.z), w3d = dup2(wv.w);
                a0 = fma2(hA.x, w0d, a0); a1 = fma2(hA.y, w0d, a1);
                a0 = fma2(hB.x, w1d, a0); a1 = fma2(hB.y, w1d, a1);
                a0 = fma2(hC.x, w2d, a0); a1 = fma2(hC.y, w2d, a1);
                a0 = fma2(hD.x, w3d, a0); a1 = fma2(hD.y, w3d, a1);
            }
            float b = bs2[ug];
            float2 p0 = unpack2(a0), p1 = unpack2(a1);
            float r0v = p0.x + b, r1v = p0.y + b, r2v = p1.x + b, r3v = p1.y + b;
            if (ph == 0) {
                o2[(4*rg+0)*16 + ug] = r0v;
                o2[(4*rg+1)*16 + ug] = r1v;
                o2[(4*rg+2)*16 + ug] = r2v;
                o2[(4*rg+3)*16 + ug] = r3v;
            } else {
                out[(size_t)(row0+4*rg+0)*12 + 9 + ug] = r0v;
                out[(size_t)(row0+4*rg+1)*12 + 9 + ug] = r1v;
                out[(size_t)(row0+4*rg+2)*12 + 9 + ug] = r2v;
                out[(size_t)(row0+4*rg+3)*12 + 9 + ug] = r3v;
            }
        }
    }

    __syncthreads();
    // expm(omega) per row: scaling & squaring + order-12 Taylor (Horner)
    if (tid < TILE_M) {
        float A[9], T[9], M[9];
        #pragma unroll
        for (int i = 0; i < 9; i++) A[i] = o2[tid*16 + i];

        float n0 = fabsf(A[0]) + fabsf(A[1]) + fabsf(A[2]);
        float n1 = fabsf(A[3]) + fabsf(A[4]) + fabsf(A[5]);
        float n2 = fabsf(A[6]) + fabsf(A[7]) + fabsf(A[8]);
        float nrm = fmaxf(n0, fmaxf(n1, n2));
        int s = 0;
        if (nrm > 0.25f) {
            s = (int)ceilf(log2f(nrm * 4.0f));
            if (s < 0) s = 0;
            float sc = exp2f(-(float)s);
            #pragma unroll
            for (int i = 0; i < 9; i++) A[i] *= sc;
        }
        // T = I + A/12
        #pragma unroll
        for (int i = 0; i < 9; i++) T[i] = A[i] * (1.0f/12.0f);
        T[0] += 1.f; T[4] += 1.f; T[8] += 1.f;
        #pragma unroll
        for (int j = 11; j >= 1; --j) {
            mat3mul(M, A, T);
            float r = 1.0f / (float)j;   // constant-folded after unroll
            #pragma unroll
            for (int i = 0; i < 9; i++) T[i] = M[i] * r;
            T[0] += 1.f; T[4] += 1.f; T[8] += 1.f;
        }
        for (int q = 0; q < s; ++q) {
            mat3mul(M, T, T);
            #pragma unroll
            for (int i = 0; i < 9; i++) T[i] = M[i];
        }
        const size_t row = (size_t)row0 + tid;
        #pragma unroll
        for (int i = 0; i < 9; i++) out[row*12 + i] = T[i];
    }
}

extern "C" void kernel_launch(void* const* d_in, const int* in_sizes, int n_in,
                              void* d_out, int out_size)
{
    const float* y   = (const float*)d_in[0];
    const float* ow0 = (const float*)d_in[1];
    const float* ob0 = (const float*)d_in[2];
    const float* ow1 = (const float*)d_in[3];
    const float* ob1 = (const float*)d_in[4];
    const float* ow2 = (const float*)d_in[5];
    const float* ob2 = (const float*)d_in[6];
    const float* tw0 = (const float*)d_in[7];
    const float* tb0 = (const float*)d_in[8];
    const float* tw1 = (const float*)d_in[9];
    const float* tb1 = (const float*)d_in[10];
    const float* tw2 = (const float*)d_in[11];
    const float* tb2 = (const float*)d_in[12];
    float* out = (float*)d_out;

    const int Bn = in_sizes[0] / 64;         // rows
    const int grid = Bn / TILE_M;            // 2048 for B=131072

    const size_t smem = (size_t)(128*32 + 128*128 + 12*128 + 128 + 128 + 16
                                 + 32*HS + 128*HS + 128*HS + 64*16) * sizeof(float);

    cudaFuncSetAttribute(l2t_kernel, cudaFuncAttributeMaxDynamicSharedMemorySize, (int)smem);

    l2t_kernel<<<grid, NTHREADS, smem>>>(y, ow0, ob0, ow1, ob1, ow2, ob2,
                                         tw0, tb0, tw1, tb1, tw2, tb2, out);
}

// round 3
// speedup vs baseline: 3.7339x; 3.7339x over previous
#include <cuda_runtime.h>
#include <cstdint>

#define NT 256
#define TILE 128
#define HSTR 132

// ---- smem layout (float offsets) ----
#define OFF_BP1 0                 // 16*4*32*2   = 4096
#define OFF_BP2 4096              // 16*16*32*2  = 16384
#define OFF_BP3 20480             // 2*16*32*2   = 2048
#define OFF_BS0 22528             // 128
#define OFF_BS1 22656             // 128
#define OFF_BS2 22784             // 16
#define OFF_H   22800             // 8*16*132    = 16896
#define SMEM_FLOATS (OFF_H + 16896)   // 39696 floats = 158784 B

__device__ __forceinline__ uint32_t cvt_tf32(float f) {
    uint32_t r; asm("cvt.rn.tf32.f32 %0, %1;" : "=r"(r) : "f"(f)); return r;
}
__device__ __forceinline__ float cvt_tf32f(float f) {
    return __uint_as_float(cvt_tf32(f));
}

__device__ __forceinline__ void mma_tf32(float& d0, float& d1, float& d2, float& d3,
                                         uint32_t a0, uint32_t a1, uint32_t a2, uint32_t a3,
                                         uint32_t b0, uint32_t b1) {
    asm("mma.sync.aligned.m16n8k8.row.col.f32.tf32.tf32.f32 "
        "{%0,%1,%2,%3}, {%4,%5,%6,%7}, {%8,%9}, {%0,%1,%2,%3};"
        : "+f"(d0), "+f"(d1), "+f"(d2), "+f"(d3)
        : "r"(a0), "r"(a1), "r"(a2), "r"(a3), "r"(b0), "r"(b1));
}

__device__ __forceinline__ void mat3mul(float* C, const float* A, const float* Bm) {
    #pragma unroll
    for (int i = 0; i < 3; i++)
        #pragma unroll
        for (int j = 0; j < 3; j++)
            C[i*3+j] = A[i*3]*Bm[j] + A[i*3+1]*Bm[3+j] + A[i*3+2]*Bm[6+j];
}

__global__ void __launch_bounds__(NT, 1)
l2t_mma_kernel(const float* __restrict__ y,
               const float* __restrict__ ow0, const float* __restrict__ ob0,
               const float* __restrict__ ow1, const float* __restrict__ ob1,
               const float* __restrict__ ow2, const float* __restrict__ ob2,
               const float* __restrict__ tw0, const float* __restrict__ tb0,
               const float* __restrict__ tw1, const float* __restrict__ tb1,
               const float* __restrict__ tw2, const float* __restrict__ tb2,
               float* __restrict__ out, int tiles)
{
    extern __shared__ float sm[];
    float* Bp1 = sm + OFF_BP1;
    float* Bp2 = sm + OFF_BP2;
    float* Bp3 = sm + OFF_BP3;
    float* bs0 = sm + OFF_BS0;
    float* bs1 = sm + OFF_BS1;
    float* bs2 = sm + OFF_BS2;

    const int tid  = threadIdx.x;
    const int wid  = tid >> 5;
    const int lane = tid & 31;
    const int qr   = lane >> 2;   // 0..7
    const int qc   = lane & 3;    // 0..3
    float* Hw = sm + OFF_H + wid * 16 * HSTR;

    #pragma unroll 1
    for (int ph = 0; ph < 2; ++ph) {
        const float* w0 = ph ? tw0 : ow0;  const float* b0 = ph ? tb0 : ob0;
        const float* w1 = ph ? tw1 : ow1;  const float* b1 = ph ? tb1 : ob1;
        const float* w2 = ph ? tw2 : ow2;  const float* b2 = ph ? tb2 : ob2;
        const int nout = ph ? 3 : 9;

        __syncthreads();   // previous phase finished reading packed weights

        // ---- pack weights into B-fragment order (tf32) ----
        // b0 = W[n][k], b1 = W[n][k+4];  n = nt*8 + lane/4, k = ks*8 + lane%4
        for (int i = tid; i < 16*4*32; i += NT) {            // W0 [128][32]
            int l = i & 31, ks = (i >> 5) & 3, nt = i >> 7;
            int n = nt*8 + (l >> 2), k = ks*8 + (l & 3);
            Bp1[i*2+0] = cvt_tf32f(w0[n*32 + k]);
            Bp1[i*2+1] = cvt_tf32f(w0[n*32 + k + 4]);
        }
        for (int i = tid; i < 16*16*32; i += NT) {           // W1 [128][128]
            int l = i & 31, ks = (i >> 5) & 15, nt = i >> 9;
            int n = nt*8 + (l >> 2), k = ks*8 + (l & 3);
            Bp2[i*2+0] = cvt_tf32f(w1[n*128 + k]);
            Bp2[i*2+1] = cvt_tf32f(w1[n*128 + k + 4]);
        }
        for (int i = tid; i < 2*16*32; i += NT) {            // W2 [nout][128], N pad 16
            int l = i & 31, ks = (i >> 5) & 15, nt = i >> 9;
            int n = nt*8 + (l >> 2), k = ks*8 + (l & 3);
            float v0 = (n < nout) ? w2[n*128 + k]     : 0.f;
            float v1 = (n < nout) ? w2[n*128 + k + 4] : 0.f;
            Bp3[i*2+0] = cvt_tf32f(v0);
            Bp3[i*2+1] = cvt_tf32f(v1);
        }
        if (tid < 128) { bs0[tid] = b0[tid]; bs1[tid] = b1[tid]; }
        if (tid < 16)  bs2[tid] = (tid < nout) ? b2[tid] : 0.f;
        __syncthreads();

        #pragma unroll 1
        for (int t = blockIdx.x; t < tiles; t += gridDim.x) {
            const int m0 = t * TILE + wid * 16;   // this warp's 16 rows

            // ---- Layer 1: A from gmem (K=32 -> 4 k-steps) ----
            uint32_t A1[4][4];
            const float* yb = y + (size_t)(m0 + qr) * 64 + ph * 32 + qc;
            #pragma unroll
            for (int ks = 0; ks < 4; ++ks) {
                A1[ks][0] = cvt_tf32(__ldg(yb + ks*8));
                A1[ks][1] = cvt_tf32(__ldg(yb + 512 + ks*8));
                A1[ks][2] = cvt_tf32(__ldg(yb + ks*8 + 4));
                A1[ks][3] = cvt_tf32(__ldg(yb + 512 + ks*8 + 4));
            }
            #pragma unroll
            for (int nt = 0; nt < 16; ++nt) {
                float d0 = 0.f, d1 = 0.f, d2 = 0.f, d3 = 0.f;
                #pragma unroll
                for (int ks = 0; ks < 4; ++ks) {
                    float2 bb = *(const float2*)(Bp1 + ((nt*4 + ks)*32 + lane)*2);
                    mma_tf32(d0, d1, d2, d3,
                             A1[ks][0], A1[ks][1], A1[ks][2], A1[ks][3],
                             __float_as_uint(bb.x), __float_as_uint(bb.y));
                }
                const int col = nt*8 + 2*qc;
                const float bv0 = bs0[col], bv1 = bs0[col+1];
                float2 lo, hi;
                lo.x = cvt_tf32f(fmaxf(d0 + bv0, 0.f));
                lo.y = cvt_tf32f(fmaxf(d1 + bv1, 0.f));
                hi.x = cvt_tf32f(fmaxf(d2 + bv0, 0.f));
                hi.y = cvt_tf32f(fmaxf(d3 + bv1, 0.f));
                *(float2*)(Hw + qr*HSTR + col)       = lo;
                *(float2*)(Hw + (qr + 8)*HSTR + col) = hi;
            }
            __syncwarp();

            // ---- Layer 2: A from Hw (K=128 -> 16 k-steps), in-place output ----
            uint32_t A2[16][4];
            #pragma unroll
            for (int ks = 0; ks < 16; ++ks) {
                A2[ks][0] = __float_as_uint(Hw[qr*HSTR + ks*8 + qc]);
                A2[ks][1] = __float_as_uint(Hw[(qr + 8)*HSTR + ks*8 + qc]);
                A2[ks][2] = __float_as_uint(Hw[qr*HSTR + ks*8 + qc + 4]);
                A2[ks][3] = __float_as_uint(Hw[(qr + 8)*HSTR + ks*8 + qc + 4]);
            }
            __syncwarp();
            #pragma unroll
            for (int nt = 0; nt < 16; ++nt) {
                float d0 = 0.f, d1 = 0.f, d2 = 0.f, d3 = 0.f;
                #pragma unroll
                for (int ks = 0; ks < 16; ++ks) {
                    float2 bb = *(const float2*)(Bp2 + ((nt*16 + ks)*32 + lane)*2);
                    mma_tf32(d0, d1, d2, d3,
                             A2[ks][0], A2[ks][1], A2[ks][2], A2[ks][3],
                             __float_as_uint(bb.x), __float_as_uint(bb.y));
                }
                const int col = nt*8 + 2*qc;
                const float bv0 = bs1[col], bv1 = bs1[col+1];
                float2 lo, hi;
                lo.x = cvt_tf32f(fmaxf(d0 + bv0, 0.f));
                lo.y = cvt_tf32f(fmaxf(d1 + bv1, 0.f));
                hi.x = cvt_tf32f(fmaxf(d2 + bv0, 0.f));
                hi.y = cvt_tf32f(fmaxf(d3 + bv1, 0.f));
                *(float2*)(Hw + qr*HSTR + col)       = lo;
                *(float2*)(Hw + (qr + 8)*HSTR + col) = hi;
            }
            __syncwarp();

            // ---- Layer 3: N=16 (9 or 3 used) ----
            uint32_t A3[16][4];
            #pragma unroll
            for (int ks = 0; ks < 16; ++ks) {
                A3[ks][0] = __float_as_uint(Hw[qr*HSTR + ks*8 + qc]);
                A3[ks][1] = __float_as_uint(Hw[(qr + 8)*HSTR + ks*8 + qc]);
                A3[ks][2] = __float_as_uint(Hw[qr*HSTR + ks*8 + qc + 4]);
                A3[ks][3] = __float_as_uint(Hw[(qr + 8)*HSTR + ks*8 + qc + 4]);
            }
            __syncwarp();
            float D3[2][4];
            #pragma unroll
            for (int nt = 0; nt < 2; ++nt) {
                D3[nt][0] = D3[nt][1] = D3[nt][2] = D3[nt][3] = 0.f;
                #pragma unroll
                for (int ks = 0; ks < 16; ++ks) {
                    float2 bb = *(const float2*)(Bp3 + ((nt*16 + ks)*32 + lane)*2);
                    mma_tf32(D3[nt][0], D3[nt][1], D3[nt][2], D3[nt][3],
                             A3[ks][0], A3[ks][1], A3[ks][2], A3[ks][3],
                             __float_as_uint(bb.x), __float_as_uint(bb.y));
                }
            }
            // stash raw f32 (+bias) into Hw cols 0..15 (A3 already in regs)
            #pragma unroll
            for (int nt = 0; nt < 2; ++nt) {
                const int col = nt*8 + 2*qc;
                Hw[qr*HSTR + col]           = D3[nt][0] + bs2[col];
                Hw[qr*HSTR + col + 1]       = D3[nt][1] + bs2[col+1];
                Hw[(qr + 8)*HSTR + col]     = D3[nt][2] + bs2[col];
                Hw[(qr + 8)*HSTR + col + 1] = D3[nt][3] + bs2[col+1];
            }
            __syncwarp();

            if (ph == 0) {
                if (lane < 16) {
                    float A[9], T[9], M[9];
                    #pragma unroll
                    for (int j = 0; j < 9; ++j) A[j] = Hw[lane*HSTR + j];

                    float n0 = fabsf(A[0]) + fabsf(A[1]) + fabsf(A[2]);
                    float n1 = fabsf(A[3]) + fabsf(A[4]) + fabsf(A[5]);
                    float n2 = fabsf(A[6]) + fabsf(A[7]) + fabsf(A[8]);
                    float nrm = fmaxf(n0, fmaxf(n1, n2));
                    int s = 0;
                    if (nrm > 0.25f) {
                        s = (int)ceilf(log2f(nrm * 4.0f));
                        if (s < 0) s = 0;
                        float sc = exp2f(-(float)s);
                        #pragma unroll
                        for (int j = 0; j < 9; ++j) A[j] *= sc;
                    }
                    #pragma unroll
                    for (int j = 0; j < 9; ++j) T[j] = A[j] * (1.0f/12.0f);
                    T[0] += 1.f; T[4] += 1.f; T[8] += 1.f;
                    #pragma unroll
                    for (int jj = 11; jj >= 1; --jj) {
                        mat3mul(M, A, T);
                        float rc = 1.0f / (float)jj;
                        #pragma unroll
                        for (int j = 0; j < 9; ++j) T[j] = M[j] * rc;
                        T[0] += 1.f; T[4] += 1.f; T[8] += 1.f;
                    }
                    for (int q = 0; q < s; ++q) {
                        mat3mul(M, T, T);
                        #pragma unroll
                        for (int j = 0; j < 9; ++j) T[j] = M[j];
                    }
                    const size_t row = (size_t)m0 + lane;
                    #pragma unroll
                    for (int j = 0; j < 9; ++j) out[row*12 + j] = T[j];
                }
            } else {
                if (lane < 16) {
                    const size_t row = (size_t)m0 + lane;
                    #pragma unroll
                    for (int j = 0; j < 3; ++j)
                        out[row*12 + 9 + j] = Hw[lane*HSTR + j];
                }
            }
            __syncwarp();  // Hw scratch reads done before next tile's layer 1
        }
    }
}

extern "C" void kernel_launch(void* const* d_in, const int* in_sizes, int n_in,
                              void* d_out, int out_size)
{
    const float* y   = (const float*)d_in[0];
    const float* ow0 = (const float*)d_in[1];
    const float* ob0 = (const float*)d_in[2];
    const float* ow1 = (const float*)d_in[3];
    const float* ob1 = (const float*)d_in[4];
    const float* ow2 = (const float*)d_in[5];
    const float* ob2 = (const float*)d_in[6];
    const float* tw0 = (const float*)d_in[7];
    const float* tb0 = (const float*)d_in[8];
    const float* tw1 = (const float*)d_in[9];
    const float* tb1 = (const float*)d_in[10];
    const float* tw2 = (const float*)d_in[11];
    const float* tb2 = (const float*)d_in[12];
    float* out = (float*)d_out;

    const int Bn = in_sizes[0] / 64;
    const int tiles = Bn / TILE;                 // 1024 for B=131072

    int sms = 148;
    cudaDeviceGetAttribute(&sms, cudaDevAttrMultiProcessorCount, 0);
    int grid = tiles < sms ? tiles : sms;

    const size_t smem = SMEM_FLOATS * sizeof(float);
    cudaFuncSetAttribute(l2t_mma_kernel, cudaFuncAttributeMaxDynamicSharedMemorySize, (int)smem);
    l2t_mma_kernel<<<grid, NT, smem>>>(y, ow0, ob0, ow1, ob1, ow2, ob2,
                                       tw0, tb0, tw1, tb1, tw2, tb2, out, tiles);
}

// round 7
// speedup vs baseline: 4.2022x; 1.1254x over previous
#include <cuda_runtime.h>
#include <cstdint>

#define NT 256
#define TILE 256      // 8 warps * 32 rows
#define HSTR 132

// ---- smem layout (float offsets) ----
#define OFF_BP1 0                 // 16*4*32*2   = 4096
#define OFF_BP2 4096              // 16*16*32*2  = 16384
#define OFF_BP3 20480             // 2*16*32*2   = 2048
#define OFF_BS0 22528             // 128
#define OFF_BS1 22656             // 128
#define OFF_BS2 22784             // 16
#define OFF_H   22800             // 8 warps * 32 rows * 132 = 33792
#define SMEM_FLOATS (OFF_H + 33792)   // 56592 floats = 226368 B

__device__ __forceinline__ uint32_t cvt_tf32(float f) {
    uint32_t r; asm("cvt.rn.tf32.f32 %0, %1;" : "=r"(r) : "f"(f)); return r;
}
__device__ __forceinline__ float cvt_tf32f(float f) {
    return __uint_as_float(cvt_tf32(f));
}

__device__ __forceinline__ void mma_tf32(float& d0, float& d1, float& d2, float& d3,
                                         uint32_t a0, uint32_t a1, uint32_t a2, uint32_t a3,
                                         uint32_t b0, uint32_t b1) {
    asm("mma.sync.aligned.m16n8k8.row.col.f32.tf32.tf32.f32 "
        "{%0,%1,%2,%3}, {%4,%5,%6,%7}, {%8,%9}, {%0,%1,%2,%3};"
        : "+f"(d0), "+f"(d1), "+f"(d2), "+f"(d3)
        : "r"(a0), "r"(a1), "r"(a2), "r"(a3), "r"(b0), "r"(b1));
}

__device__ __forceinline__ void mat3mul(float* C, const float* A, const float* Bm) {
    #pragma unroll
    for (int i = 0; i < 3; i++)
        #pragma unroll
        for (int j = 0; j < 3; j++)
            C[i*3+j] = A[i*3]*Bm[j] + A[i*3+1]*Bm[3+j] + A[i*3+2]*Bm[6+j];
}

__global__ void __launch_bounds__(NT, 1)
l2t_mma_kernel(const float* __restrict__ y,
               const float* __restrict__ ow0, const float* __restrict__ ob0,
               const float* __restrict__ ow1, const float* __restrict__ ob1,
               const float* __restrict__ ow2, const float* __restrict__ ob2,
               const float* __restrict__ tw0, const float* __restrict__ tb0,
               const float* __restrict__ tw1, const float* __restrict__ tb1,
               const float* __restrict__ tw2, const float* __restrict__ tb2,
               float* __restrict__ out, int tiles)
{
    extern __shared__ float sm[];
    float* Bp1 = sm + OFF_BP1;
    float* Bp2 = sm + OFF_BP2;
    float* Bp3 = sm + OFF_BP3;
    float* bs0 = sm + OFF_BS0;
    float* bs1 = sm + OFF_BS1;
    float* bs2 = sm + OFF_BS2;

    const int tid  = threadIdx.x;
    const int wid  = tid >> 5;
    const int lane = tid & 31;
    const int qr   = lane >> 2;   // 0..7
    const int qc   = lane & 3;    // 0..3
    float* Hw = sm + OFF_H + wid * 32 * HSTR;   // this warp's 32 rows

    #pragma unroll 1
    for (int ph = 0; ph < 2; ++ph) {
        const float* w0 = ph ? tw0 : ow0;  const float* b0 = ph ? tb0 : ob0;
        const float* w1 = ph ? tw1 : ow1;  const float* b1 = ph ? tb1 : ob1;
        const float* w2 = ph ? tw2 : ow2;  const float* b2 = ph ? tb2 : ob2;
        const int nout = ph ? 3 : 9;

        __syncthreads();   // previous phase finished reading packed weights

        // ---- pack weights into B-fragment order (tf32) ----
        for (int i = tid; i < 16*4*32; i += NT) {            // W0 [128][32]
            int l = i & 31, ks = (i >> 5) & 3, nt = i >> 7;
            int n = nt*8 + (l >> 2), k = ks*8 + (l & 3);
            Bp1[i*2+0] = cvt_tf32f(w0[n*32 + k]);
            Bp1[i*2+1] = cvt_tf32f(w0[n*32 + k + 4]);
        }
        for (int i = tid; i < 16*16*32; i += NT) {           // W1 [128][128]
            int l = i & 31, ks = (i >> 5) & 15, nt = i >> 9;
            int n = nt*8 + (l >> 2), k = ks*8 + (l & 3);
            Bp2[i*2+0] = cvt_tf32f(w1[n*128 + k]);
            Bp2[i*2+1] = cvt_tf32f(w1[n*128 + k + 4]);
        }
        for (int i = tid; i < 2*16*32; i += NT) {            // W2 [nout][128], N pad 16
            int l = i & 31, ks = (i >> 5) & 15, nt = i >> 9;
            int n = nt*8 + (l >> 2), k = ks*8 + (l & 3);
            float v0 = (n < nout) ? w2[n*128 + k]     : 0.f;
            float v1 = (n < nout) ? w2[n*128 + k + 4] : 0.f;
            Bp3[i*2+0] = cvt_tf32f(v0);
            Bp3[i*2+1] = cvt_tf32f(v1);
        }
        if (tid < 128) { bs0[tid] = b0[tid]; bs1[tid] = b1[tid]; }
        if (tid < 16)  bs2[tid] = (tid < nout) ? b2[tid] : 0.f;
        __syncthreads();

        #pragma unroll 1
        for (int t = blockIdx.x; t < tiles; t += gridDim.x) {
            const int m0 = t * TILE + wid * 32;   // this warp's 32 rows

            // ---- Layer 1: A from gmem (two 16-row groups, K=32) ----
            uint32_t A1[2][4][4];
            #pragma unroll
            for (int g = 0; g < 2; ++g) {
                const float* yb = y + (size_t)(m0 + g*16 + qr) * 64 + ph * 32 + qc;
                #pragma unroll
                for (int ks = 0; ks < 4; ++ks) {
                    A1[g][ks][0] = cvt_tf32(__ldg(yb + ks*8));
                    A1[g][ks][1] = cvt_tf32(__ldg(yb + 512 + ks*8));
                    A1[g][ks][2] = cvt_tf32(__ldg(yb + ks*8 + 4));
                    A1[g][ks][3] = cvt_tf32(__ldg(yb + 512 + ks*8 + 4));
                }
            }
            #pragma unroll
            for (int nt = 0; nt < 16; ++nt) {
                float d[2][4] = {{0.f,0.f,0.f,0.f},{0.f,0.f,0.f,0.f}};
                #pragma unroll
                for (int ks = 0; ks < 4; ++ks) {
                    float2 bb = *(const float2*)(Bp1 + ((nt*4 + ks)*32 + lane)*2);
                    uint32_t b0r = __float_as_uint(bb.x), b1r = __float_as_uint(bb.y);
                    mma_tf32(d[0][0], d[0][1], d[0][2], d[0][3],
                             A1[0][ks][0], A1[0][ks][1], A1[0][ks][2], A1[0][ks][3], b0r, b1r);
                    mma_tf32(d[1][0], d[1][1], d[1][2], d[1][3],
                             A1[1][ks][0], A1[1][ks][1], A1[1][ks][2], A1[1][ks][3], b0r, b1r);
                }
                const int col = nt*8 + 2*qc;
                const float bv0 = bs0[col], bv1 = bs0[col+1];
                #pragma unroll
                for (int g = 0; g < 2; ++g) {
                    float2 lo, hi;
                    lo.x = cvt_tf32f(fmaxf(d[g][0] + bv0, 0.f));
                    lo.y = cvt_tf32f(fmaxf(d[g][1] + bv1, 0.f));
                    hi.x = cvt_tf32f(fmaxf(d[g][2] + bv0, 0.f));
                    hi.y = cvt_tf32f(fmaxf(d[g][3] + bv1, 0.f));
                    *(float2*)(Hw + (g*16 + qr)*HSTR + col)     = lo;
                    *(float2*)(Hw + (g*16 + qr + 8)*HSTR + col) = hi;
                }
            }
            __syncwarp();

            // ---- Layer 2: A from Hw (K=128), in-place output ----
            uint32_t Ar[2][16][4];
            #pragma unroll
            for (int g = 0; g < 2; ++g)
                #pragma unroll
                for (int ks = 0; ks < 16; ++ks) {
                    Ar[g][ks][0] = __float_as_uint(Hw[(g*16 + qr)*HSTR + ks*8 + qc]);
                    Ar[g][ks][1] = __float_as_uint(Hw[(g*16 + qr + 8)*HSTR + ks*8 + qc]);
                    Ar[g][ks][2] = __float_as_uint(Hw[(g*16 + qr)*HSTR + ks*8 + qc + 4]);
                    Ar[g][ks][3] = __float_as_uint(Hw[(g*16 + qr + 8)*HSTR + ks*8 + qc + 4]);
                }
            __syncwarp();
            #pragma unroll
            for (int nt = 0; nt < 16; ++nt) {
                float d[2][4] = {{0.f,0.f,0.f,0.f},{0.f,0.f,0.f,0.f}};
                #pragma unroll
                for (int ks = 0; ks < 16; ++ks) {
                    float2 bb = *(const float2*)(Bp2 + ((nt*16 + ks)*32 + lane)*2);
                    uint32_t b0r = __float_as_uint(bb.x), b1r = __float_as_uint(bb.y);
                    mma_tf32(d[0][0], d[0][1], d[0][2], d[0][3],
                             Ar[0][ks][0], Ar[0][ks][1], Ar[0][ks][2], Ar[0][ks][3], b0r, b1r);
                    mma_tf32(d[1][0], d[1][1], d[1][2], d[1][3],
                             Ar[1][ks][0], Ar[1][ks][1], Ar[1][ks][2], Ar[1][ks][3], b0r, b1r);
                }
                const int col = nt*8 + 2*qc;
                const float bv0 = bs1[col], bv1 = bs1[col+1];
                #pragma unroll
                for (int g = 0; g < 2; ++g) {
                    float2 lo, hi;
                    lo.x = cvt_tf32f(fmaxf(d[g][0] + bv0, 0.f));
                    lo.y = cvt_tf32f(fmaxf(d[g][1] + bv1, 0.f));
                    hi.x = cvt_tf32f(fmaxf(d[g][2] + bv0, 0.f));
                    hi.y = cvt_tf32f(fmaxf(d[g][3] + bv1, 0.f));
                    *(float2*)(Hw + (g*16 + qr)*HSTR + col)     = lo;
                    *(float2*)(Hw + (g*16 + qr + 8)*HSTR + col) = hi;
                }
            }
            __syncwarp();

            // ---- Layer 3: reload A (reuse Ar), N=16 ----
            #pragma unroll
            for (int g = 0; g < 2; ++g)
                #pragma unroll
                for (int ks = 0; ks < 16; ++ks) {
                    Ar[g][ks][0] = __float_as_uint(Hw[(g*16 + qr)*HSTR + ks*8 + qc]);
                    Ar[g][ks][1] = __float_as_uint(Hw[(g*16 + qr + 8)*HSTR + ks*8 + qc]);
                    Ar[g][ks][2] = __float_as_uint(Hw[(g*16 + qr)*HSTR + ks*8 + qc + 4]);
                    Ar[g][ks][3] = __float_as_uint(Hw[(g*16 + qr + 8)*HSTR + ks*8 + qc + 4]);
                }
            __syncwarp();
            #pragma unroll
            for (int nt = 0; nt < 2; ++nt) {
                float d[2][4] = {{0.f,0.f,0.f,0.f},{0.f,0.f,0.f,0.f}};
                #pragma unroll
                for (int ks = 0; ks < 16; ++ks) {
                    float2 bb = *(const float2*)(Bp3 + ((nt*16 + ks)*32 + lane)*2);
                    uint32_t b0r = __float_as_uint(bb.x), b1r = __float_as_uint(bb.y);
                    mma_tf32(d[0][0], d[0][1], d[0][2], d[0][3],
                             Ar[0][ks][0], Ar[0][ks][1], Ar[0][ks][2], Ar[0][ks][3], b0r, b1r);
                    mma_tf32(d[1][0], d[1][1], d[1][2], d[1][3],
                             Ar[1][ks][0], Ar[1][ks][1], Ar[1][ks][2], Ar[1][ks][3], b0r, b1r);
                }
                const int col = nt*8 + 2*qc;
                #pragma unroll
                for (int g = 0; g < 2; ++g) {
                    Hw[(g*16 + qr)*HSTR + col]           = d[g][0] + bs2[col];
                    Hw[(g*16 + qr)*HSTR + col + 1]       = d[g][1] + bs2[col+1];
                    Hw[(g*16 + qr + 8)*HSTR + col]       = d[g][2] + bs2[col];
                    Hw[(g*16 + qr + 8)*HSTR + col + 1]   = d[g][3] + bs2[col+1];
                }
            }
            __syncwarp();

            // ---- epilogue: one row per lane (all 32 lanes) ----
            if (ph == 0) {
                float A[9], T[9], M[9];
                #pragma unroll
                for (int j = 0; j < 9; ++j) A[j] = Hw[lane*HSTR + j];

                float n0 = fabsf(A[0]) + fabsf(A[1]) + fabsf(A[2]);
                float n1 = fabsf(A[3]) + fabsf(A[4]) + fabsf(A[5]);
                float n2 = fabsf(A[6]) + fabsf(A[7]) + fabsf(A[8]);
                float nrm = fmaxf(n0, fmaxf(n1, n2));
                int s = 0;
                if (nrm > 0.25f) {
                    s = (int)ceilf(log2f(nrm * 4.0f));
                    if (s < 0) s = 0;
                    float sc = exp2f(-(float)s);
                    #pragma unroll
                    for (int j = 0; j < 9; ++j) A[j] *= sc;
                }
                #pragma unroll
                for (int j = 0; j < 9; ++j) T[j] = A[j] * (1.0f/12.0f);
                T[0] += 1.f; T[4] += 1.f; T[8] += 1.f;
                #pragma unroll
                for (int jj = 11; jj >= 1; --jj) {
                    mat3mul(M, A, T);
                    float rc = 1.0f / (float)jj;
                    #pragma unroll
                    for (int j = 0; j < 9; ++j) T[j] = M[j] * rc;
                    T[0] += 1.f; T[4] += 1.f; T[8] += 1.f;
                }
                for (int q = 0; q < s; ++q) {
                    mat3mul(M, T, T);
                    #pragma unroll
                    for (int j = 0; j < 9; ++j) T[j] = M[j];
                }
                const size_t row = (size_t)m0 + lane;
                #pragma unroll
                for (int j = 0; j < 9; ++j) out[row*12 + j] = T[j];
            } else {
                const size_t row = (size_t)m0 + lane;
                #pragma unroll
                for (int j = 0; j < 3; ++j)
                    out[row*12 + 9 + j] = Hw[lane*HSTR + j];
            }
            __syncwarp();  // Hw scratch reads done before next tile's layer 1
        }
    }
}

extern "C" void kernel_launch(void* const* d_in, const int* in_sizes, int n_in,
                              void* d_out, int out_size)
{
    const float* y   = (const float*)d_in[0];
    const float* ow0 = (const float*)d_in[1];
    const float* ob0 = (const float*)d_in[2];
    const float* ow1 = (const float*)d_in[3];
    const float* ob1 = (const float*)d_in[4];
    const float* ow2 = (const float*)d_in[5];
    const float* ob2 = (const float*)d_in[6];
    const float* tw0 = (const float*)d_in[7];
    const float* tb0 = (const float*)d_in[8];
    const float* tw1 = (const float*)d_in[9];
    const float* tb1 = (const float*)d_in[10];
    const float* tw2 = (const float*)d_in[11];
    const float* tb2 = (const float*)d_in[12];
    float* out = (float*)d_out;

    const int Bn = in_sizes[0] / 64;
    const int tiles = Bn / TILE;                 // 512 for B=131072

    int sms = 148;
    cudaDeviceGetAttribute(&sms, cudaDevAttrMultiProcessorCount, 0);
    int grid = tiles < sms ? tiles : sms;

    const size_t smem = SMEM_FLOATS * sizeof(float);
    cudaFuncSetAttribute(l2t_mma_kernel, cudaFuncAttributeMaxDynamicSharedMemorySize, (int)smem);
    l2t_mma_kernel<<<grid, NT, smem>>>(y, ow0, ob0, ow1, ob1, ow2, ob2,
                                       tw0, tb0, tw1, tb1, tw2, tb2, out, tiles);
}